// round 9
// baseline (speedup 1.0000x reference)
#include <cuda_runtime.h>

#define NPTS    4096
#define NB      8
#define NIC     16        // i-chunks of 256 queries
#define NJH     8         // j-segments of 512 targets
#define JSEG    512
#define THREADS 128
#define NPART   64        // ic*4 + warp  (64 i's per warp-part)
#define BIAS    128.0f

// stage1 -> stage2 partials (static device arrays: allocation-free)
__device__ float g_colpart[NB * NPART * NPTS];   // [b][part][j], 8.4 MB
__device__ float g_rowpart[NB * NPTS * NJH];     // [b][i][jh],   1 MB
__device__ float g_final[160];

// ---- packed f32x2 + redux helpers ----
__device__ __forceinline__ double pack2(float lo, float hi) {
    double d; asm("mov.b64 %0, {%1, %2};" : "=d"(d) : "f"(lo), "f"(hi)); return d;
}
__device__ __forceinline__ double fma2(double a, double b, double c) {
    double d; asm("fma.rn.f32x2 %0, %1, %2, %3;" : "=d"(d) : "d"(a), "d"(b), "d"(c)); return d;
}
__device__ __forceinline__ double add2(double a, double b) {
    double d; asm("add.rn.f32x2 %0, %1, %2;" : "=d"(d) : "d"(a), "d"(b)); return d;
}
__device__ __forceinline__ void unpack2(double d, float& lo, float& hi) {
    asm("mov.b64 {%0, %1}, %2;" : "=f"(lo), "=f"(hi) : "d"(d));
}
__device__ __forceinline__ void lds_v2b64(double& a, double& b, unsigned addr) {
    asm volatile("ld.shared.v2.b64 {%0, %1}, [%2];" : "=d"(a), "=d"(b) : "r"(addr));
}
__device__ __forceinline__ unsigned redux_min_u32(unsigned v) {
    unsigned r; asm("redux.sync.min.u32 %0, %1, 0xffffffff;" : "=r"(r) : "r"(v)); return r;
}

// Stage 1: block = (b, i-chunk of 256, j-segment of 512). Each pdist tile is
// computed ONCE, biased positive: d''' = |x_i - y_j|^2 + 128, via
//   d''' = (-2qx)tx + (-2qy)ty + (-2qz)tz + ((t^2+128) + q^2)
// Row mins (over j) accumulate in registers (2 queries/thread).
// Col mins (over i) use redux.sync.min.u32 per (warp, j) -> per-part gmem.
// 1024 blocks x 4 warps, 8 resident/SM -> SINGLE wave across 148 SMs.
__global__ __launch_bounds__(THREADS, 8)
void chamfer_stage1(const float* __restrict__ x, const float* __restrict__ y) {
    __shared__ __align__(16) float sm[4 * JSEG];   // planes: tx, ty, tz, t^2+BIAS

    const int blk = blockIdx.x;
    const int jh  = blk & 7;
    const int ic  = (blk >> 3) & 15;
    const int b   = blk >> 7;

    const float* __restrict__ q = x + b * NPTS * 3;
    const float* __restrict__ t = y + b * NPTS * 3;
    const int j0 = jh * JSEG;

    for (int i = threadIdx.x; i < JSEG; i += THREADS) {
        const float tx = t[(j0 + i) * 3 + 0];
        const float ty = t[(j0 + i) * 3 + 1];
        const float tz = t[(j0 + i) * 3 + 2];
        sm[i] = tx; sm[JSEG + i] = ty; sm[2 * JSEG + i] = tz;
        sm[3 * JSEG + i] = tx * tx + ty * ty + tz * tz + BIAS;
    }
    __syncthreads();

    const int i1 = ic * 256 + threadIdx.x;
    const int i2 = i1 + THREADS;
    const float ax = q[i1 * 3 + 0], ay = q[i1 * 3 + 1], az = q[i1 * 3 + 2];
    const float bx = q[i2 * 3 + 0], by = q[i2 * 3 + 1], bz = q[i2 * 3 + 2];

    const double pAx = pack2(-2.f * ax, -2.f * ax);
    const double pAy = pack2(-2.f * ay, -2.f * ay);
    const double pAz = pack2(-2.f * az, -2.f * az);
    const double pBx = pack2(-2.f * bx, -2.f * bx);
    const double pBy = pack2(-2.f * by, -2.f * by);
    const double pBz = pack2(-2.f * bz, -2.f * bz);
    const float qsqA = ax * ax + ay * ay + az * az;
    const float qsqB = bx * bx + by * by + bz * bz;
    const double pQA = pack2(qsqA, qsqA);
    const double pQB = pack2(qsqB, qsqB);

    float rA0 = 1e30f, rA1 = 1e30f, rA2 = 1e30f, rA3 = 1e30f;
    float rB0 = 1e30f, rB1 = 1e30f, rB2 = 1e30f, rB3 = 1e30f;

    const int wid = threadIdx.x >> 5;
    const bool lane0 = (threadIdx.x & 31) == 0;
    float4* __restrict__ colout =
        (float4*)&g_colpart[(b * NPART + ic * 4 + wid) * NPTS + j0];

    unsigned a = (unsigned)__cvta_generic_to_shared(sm);

#pragma unroll 4
    for (int k = 0; k < JSEG / 4; k++, a += 16) {
        double x01, x23, y01, y23, z01, z23, w01, w23;
        lds_v2b64(x01, x23, a);
        lds_v2b64(y01, y23, a + 2048u);
        lds_v2b64(z01, z23, a + 4096u);
        lds_v2b64(w01, w23, a + 6144u);

        const double tA01 = add2(w01, pQA), tA23 = add2(w23, pQA);
        const double tB01 = add2(w01, pQB), tB23 = add2(w23, pQB);

        const double dA0 = fma2(pAx, x01, fma2(pAy, y01, fma2(pAz, z01, tA01)));
        const double dA1 = fma2(pAx, x23, fma2(pAy, y23, fma2(pAz, z23, tA23)));
        const double dB0 = fma2(pBx, x01, fma2(pBy, y01, fma2(pBz, z01, tB01)));
        const double dB1 = fma2(pBx, x23, fma2(pBy, y23, fma2(pBz, z23, tB23)));

        float a0, a1, a2, a3, b0, b1, b2, b3;
        unpack2(dA0, a0, a1); unpack2(dA1, a2, a3);
        unpack2(dB0, b0, b1); unpack2(dB1, b2, b3);

        rA0 = fminf(rA0, a0); rA1 = fminf(rA1, a1);
        rA2 = fminf(rA2, a2); rA3 = fminf(rA3, a3);
        rB0 = fminf(rB0, b0); rB1 = fminf(rB1, b1);
        rB2 = fminf(rB2, b2); rB3 = fminf(rB3, b3);

        // col mins over this warp's 64 i's; d''' > 0 so u32-min == float-min
        const unsigned c0 = redux_min_u32(__float_as_uint(fminf(a0, b0)));
        const unsigned c1 = redux_min_u32(__float_as_uint(fminf(a1, b1)));
        const unsigned c2 = redux_min_u32(__float_as_uint(fminf(a2, b2)));
        const unsigned c3 = redux_min_u32(__float_as_uint(fminf(a3, b3)));
        if (lane0)
            colout[k] = make_float4(__uint_as_float(c0), __uint_as_float(c1),
                                    __uint_as_float(c2), __uint_as_float(c3));
    }

    const float rowA = fminf(fminf(rA0, rA1), fminf(rA2, rA3));
    const float rowB = fminf(fminf(rB0, rB1), fminf(rB2, rB3));
    g_rowpart[(b * NPTS + i1) * NJH + jh] = rowA;
    g_rowpart[(b * NPTS + i2) * NJH + jh] = rowB;
}

__device__ __forceinline__ void block_sum_to(float local, int slot) {
    __shared__ float red[8];
#pragma unroll
    for (int o = 16; o; o >>= 1) local += __shfl_down_sync(0xFFFFFFFFu, local, o);
    if ((threadIdx.x & 31) == 0) red[threadIdx.x >> 5] = local;
    __syncthreads();
    if (threadIdx.x == 0) {
        float s = ((red[0] + red[1]) + (red[2] + red[3]))
                + ((red[4] + red[5]) + (red[6] + red[7]));
        g_final[slot] = s;
    }
}

// Stage 2: blocks 0..127 = col side (b, j-slice of 256): min over 64 parts,
// unbias, sum. Blocks 128..143 = row side (b, i-half): min over 8 jh, sum.
__global__ __launch_bounds__(256)
void chamfer_stage2() {
    float local = 0.f;
    if (blockIdx.x < 128) {
        const int b = blockIdx.x >> 4;
        const int j = (blockIdx.x & 15) * 256 + threadIdx.x;
        float m0 = 1e30f;
        const float* base = &g_colpart[b * NPART * NPTS];
#pragma unroll 16
        for (int p = 0; p < NPART; p++)
            m0 = fminf(m0, base[p * NPTS + j]);
        local = m0 - BIAS;
    } else {
        const int blk2 = blockIdx.x - 128;   // 0..15
        const int b = blk2 >> 1;
        const int ibase = (blk2 & 1) * 2048;
        for (int i = ibase + threadIdx.x; i < ibase + 2048; i += 256) {
            const float4* r = (const float4*)&g_rowpart[(b * NPTS + i) * NJH];
            const float4 v0 = r[0], v1 = r[1];
            const float m = fminf(fminf(fminf(v0.x, v0.y), fminf(v0.z, v0.w)),
                                  fminf(fminf(v1.x, v1.y), fminf(v1.z, v1.w)));
            local += m - BIAS;
        }
    }
    block_sum_to(local, blockIdx.x);
}

// Stage 3: sum the 144 partials, scale: loss = sum * 0.005 / 32768
__global__ void chamfer_stage3(float* __restrict__ out) {
    __shared__ float red[5];
    float v = (threadIdx.x < 144) ? g_final[threadIdx.x] : 0.f;
#pragma unroll
    for (int o = 16; o; o >>= 1) v += __shfl_down_sync(0xFFFFFFFFu, v, o);
    if ((threadIdx.x & 31) == 0) red[threadIdx.x >> 5] = v;
    __syncthreads();
    if (threadIdx.x == 0) {
        float s = (((red[0] + red[1]) + (red[2] + red[3])) + red[4]);
        out[0] = s * (0.005f / 32768.f);
    }
}

extern "C" void kernel_launch(void* const* d_in, const int* in_sizes, int n_in,
                              void* d_out, int out_size) {
    const float* x = (const float*)d_in[0];
    const float* y = (const float*)d_in[1];
    float* out = (float*)d_out;
    chamfer_stage1<<<NB * NIC * NJH, THREADS>>>(x, y);
    chamfer_stage2<<<144, 256>>>();
    chamfer_stage3<<<1, 160>>>(out);
}

// round 10
// speedup vs baseline: 1.0576x; 1.0576x over previous
#include <cuda_runtime.h>

#define NPTS    4096
#define NB      8
#define NIC     16        // i-chunks of 256 queries
#define NJH     16        // j-segments of 256 targets
#define JSEG    256
#define THREADS 128
#define NPART   64        // ic*4 + warp  (64 i's per warp-part)
#define BIAS    128.0f

// stage1 -> stage2 partials (static device arrays: allocation-free)
__device__ float g_colpart[NB * NPART * NPTS];   // [b][part][j], 8.4 MB
__device__ float g_rowpart[NB * NPTS * NJH];     // [b][i][jh],   2 MB
__device__ float g_final[160];

// ---- packed f32x2 + redux helpers ----
__device__ __forceinline__ double pack2(float lo, float hi) {
    double d; asm("mov.b64 %0, {%1, %2};" : "=d"(d) : "f"(lo), "f"(hi)); return d;
}
__device__ __forceinline__ double fma2(double a, double b, double c) {
    double d; asm("fma.rn.f32x2 %0, %1, %2, %3;" : "=d"(d) : "d"(a), "d"(b), "d"(c)); return d;
}
__device__ __forceinline__ double add2(double a, double b) {
    double d; asm("add.rn.f32x2 %0, %1, %2;" : "=d"(d) : "d"(a), "d"(b)); return d;
}
__device__ __forceinline__ void unpack2(double d, float& lo, float& hi) {
    asm("mov.b64 {%0, %1}, %2;" : "=f"(lo), "=f"(hi) : "d"(d));
}
__device__ __forceinline__ void lds_v2b64(double& a, double& b, unsigned addr) {
    asm volatile("ld.shared.v2.b64 {%0, %1}, [%2];" : "=d"(a), "=d"(b) : "r"(addr));
}
__device__ __forceinline__ unsigned redux_min_u32(unsigned v) {
    unsigned r; asm("redux.sync.min.u32 %0, %1, 0xffffffff;" : "=r"(r) : "r"(v)); return r;
}

// Stage 1: block = (b, i-chunk of 256, j-segment of 256). Each pdist tile is
// computed ONCE, biased positive: d''' = |x_i - y_j|^2 + 128, via
//   d''' = (-2qx)tx + (-2qy)ty + (-2qz)tz + ((t^2+128) + q^2)
// Row mins (over j) accumulate in registers (2 queries/thread).
// Col mins (over i) use redux.sync.min.u32 per (warp, j) -> per-part gmem.
// launch_bounds(128, 6): 84 regs/thread so ptxas can software-pipeline the
// LDS -> fma2 -> redux chain across iterations (64-reg cap was throttling ILP).
__global__ __launch_bounds__(THREADS, 6)
void chamfer_stage1(const float* __restrict__ x, const float* __restrict__ y) {
    __shared__ __align__(16) float sm[4 * JSEG];   // planes: tx, ty, tz, t^2+BIAS

    const int blk = blockIdx.x;
    const int jh  = blk & 15;
    const int ic  = (blk >> 4) & 15;
    const int b   = blk >> 8;

    const float* __restrict__ q = x + b * NPTS * 3;
    const float* __restrict__ t = y + b * NPTS * 3;
    const int j0 = jh * JSEG;

    for (int i = threadIdx.x; i < JSEG; i += THREADS) {
        const float tx = t[(j0 + i) * 3 + 0];
        const float ty = t[(j0 + i) * 3 + 1];
        const float tz = t[(j0 + i) * 3 + 2];
        sm[i] = tx; sm[JSEG + i] = ty; sm[2 * JSEG + i] = tz;
        sm[3 * JSEG + i] = tx * tx + ty * ty + tz * tz + BIAS;
    }
    __syncthreads();

    const int i1 = ic * 256 + threadIdx.x;
    const int i2 = i1 + THREADS;
    const float ax = q[i1 * 3 + 0], ay = q[i1 * 3 + 1], az = q[i1 * 3 + 2];
    const float bx = q[i2 * 3 + 0], by = q[i2 * 3 + 1], bz = q[i2 * 3 + 2];

    const double pAx = pack2(-2.f * ax, -2.f * ax);
    const double pAy = pack2(-2.f * ay, -2.f * ay);
    const double pAz = pack2(-2.f * az, -2.f * az);
    const double pBx = pack2(-2.f * bx, -2.f * bx);
    const double pBy = pack2(-2.f * by, -2.f * by);
    const double pBz = pack2(-2.f * bz, -2.f * bz);
    const float qsqA = ax * ax + ay * ay + az * az;
    const float qsqB = bx * bx + by * by + bz * bz;
    const double pQA = pack2(qsqA, qsqA);
    const double pQB = pack2(qsqB, qsqB);

    float rA0 = 1e30f, rA1 = 1e30f, rA2 = 1e30f, rA3 = 1e30f;
    float rB0 = 1e30f, rB1 = 1e30f, rB2 = 1e30f, rB3 = 1e30f;

    const int wid = threadIdx.x >> 5;
    const bool lane0 = (threadIdx.x & 31) == 0;
    float4* __restrict__ colout =
        (float4*)&g_colpart[(b * NPART + ic * 4 + wid) * NPTS + j0];

    unsigned a = (unsigned)__cvta_generic_to_shared(sm);

#pragma unroll 8
    for (int k = 0; k < JSEG / 4; k++, a += 16) {
        double x01, x23, y01, y23, z01, z23, w01, w23;
        lds_v2b64(x01, x23, a);
        lds_v2b64(y01, y23, a + 1024u);
        lds_v2b64(z01, z23, a + 2048u);
        lds_v2b64(w01, w23, a + 3072u);

        const double tA01 = add2(w01, pQA), tA23 = add2(w23, pQA);
        const double tB01 = add2(w01, pQB), tB23 = add2(w23, pQB);

        const double dA0 = fma2(pAx, x01, fma2(pAy, y01, fma2(pAz, z01, tA01)));
        const double dA1 = fma2(pAx, x23, fma2(pAy, y23, fma2(pAz, z23, tA23)));
        const double dB0 = fma2(pBx, x01, fma2(pBy, y01, fma2(pBz, z01, tB01)));
        const double dB1 = fma2(pBx, x23, fma2(pBy, y23, fma2(pBz, z23, tB23)));

        float a0, a1, a2, a3, b0, b1, b2, b3;
        unpack2(dA0, a0, a1); unpack2(dA1, a2, a3);
        unpack2(dB0, b0, b1); unpack2(dB1, b2, b3);

        rA0 = fminf(rA0, a0); rA1 = fminf(rA1, a1);
        rA2 = fminf(rA2, a2); rA3 = fminf(rA3, a3);
        rB0 = fminf(rB0, b0); rB1 = fminf(rB1, b1);
        rB2 = fminf(rB2, b2); rB3 = fminf(rB3, b3);

        // col mins over this warp's 64 i's; d''' > 0 so u32-min == float-min
        const unsigned c0 = redux_min_u32(__float_as_uint(fminf(a0, b0)));
        const unsigned c1 = redux_min_u32(__float_as_uint(fminf(a1, b1)));
        const unsigned c2 = redux_min_u32(__float_as_uint(fminf(a2, b2)));
        const unsigned c3 = redux_min_u32(__float_as_uint(fminf(a3, b3)));
        if (lane0)
            colout[k] = make_float4(__uint_as_float(c0), __uint_as_float(c1),
                                    __uint_as_float(c2), __uint_as_float(c3));
    }

    const float rowA = fminf(fminf(rA0, rA1), fminf(rA2, rA3));
    const float rowB = fminf(fminf(rB0, rB1), fminf(rB2, rB3));
    g_rowpart[(b * NPTS + i1) * NJH + jh] = rowA;
    g_rowpart[(b * NPTS + i2) * NJH + jh] = rowB;
}

__device__ __forceinline__ void block_sum_to(float local, int slot) {
    __shared__ float red[8];
#pragma unroll
    for (int o = 16; o; o >>= 1) local += __shfl_down_sync(0xFFFFFFFFu, local, o);
    if ((threadIdx.x & 31) == 0) red[threadIdx.x >> 5] = local;
    __syncthreads();
    if (threadIdx.x == 0) {
        float s = ((red[0] + red[1]) + (red[2] + red[3]))
                + ((red[4] + red[5]) + (red[6] + red[7]));
        g_final[slot] = s;
    }
}

// Stage 2: blocks 0..127 = col side (b, j-slice of 256): min over 64 parts,
// unbias, sum. Blocks 128..143 = row side (b, i-half): min over 16 jh, sum.
__global__ __launch_bounds__(256)
void chamfer_stage2() {
    float local = 0.f;
    if (blockIdx.x < 128) {
        const int b = blockIdx.x >> 4;
        const int j = (blockIdx.x & 15) * 256 + threadIdx.x;
        float m0 = 1e30f;
        const float* base = &g_colpart[b * NPART * NPTS];
#pragma unroll 16
        for (int p = 0; p < NPART; p++)
            m0 = fminf(m0, base[p * NPTS + j]);
        local = m0 - BIAS;
    } else {
        const int blk2 = blockIdx.x - 128;   // 0..15
        const int b = blk2 >> 1;
        const int ibase = (blk2 & 1) * 2048;
        for (int i = ibase + threadIdx.x; i < ibase + 2048; i += 256) {
            const float4* r = (const float4*)&g_rowpart[(b * NPTS + i) * NJH];
            const float4 v0 = r[0], v1 = r[1], v2 = r[2], v3 = r[3];
            float m = fminf(fminf(fminf(v0.x, v0.y), fminf(v0.z, v0.w)),
                            fminf(fminf(v1.x, v1.y), fminf(v1.z, v1.w)));
            m = fminf(m, fminf(fminf(fminf(v2.x, v2.y), fminf(v2.z, v2.w)),
                               fminf(fminf(v3.x, v3.y), fminf(v3.z, v3.w))));
            local += m - BIAS;
        }
    }
    block_sum_to(local, blockIdx.x);
}

// Stage 3: sum the 144 partials, scale: loss = sum * 0.005 / 32768
__global__ void chamfer_stage3(float* __restrict__ out) {
    __shared__ float red[5];
    float v = (threadIdx.x < 144) ? g_final[threadIdx.x] : 0.f;
#pragma unroll
    for (int o = 16; o; o >>= 1) v += __shfl_down_sync(0xFFFFFFFFu, v, o);
    if ((threadIdx.x & 31) == 0) red[threadIdx.x >> 5] = v;
    __syncthreads();
    if (threadIdx.x == 0) {
        float s = (((red[0] + red[1]) + (red[2] + red[3])) + red[4]);
        out[0] = s * (0.005f / 32768.f);
    }
}

extern "C" void kernel_launch(void* const* d_in, const int* in_sizes, int n_in,
                              void* d_out, int out_size) {
    const float* x = (const float*)d_in[0];
    const float* y = (const float*)d_in[1];
    float* out = (float*)d_out;
    chamfer_stage1<<<NB * NIC * NJH, THREADS>>>(x, y);
    chamfer_stage2<<<144, 256>>>();
    chamfer_stage3<<<1, 160>>>(out);
}